// round 13
// baseline (speedup 1.0000x reference)
#include <cuda_runtime.h>
#include <math.h>

#define NN 20000
#define NE 640000
#define D  128
#define TE 32
#define TN 32
#define FR16 2048  // fragment region: 16 ksteps * 128 words
#define WSZ 16384  // floats per permuted 128x128 weight

typedef unsigned int u32;

// ---------------- scratch (static device memory; no allocations) ----------------
__device__ float g_hh[NN * D];
__device__ float g_agg[NN * D];
__device__ float g_aggx[NN * 3];
__device__ float g_e3[NE * 3];        // indexed by SORTED position
__device__ float g_Pr[NN * D];
__device__ float g_Pc[NN * D];
__device__ float g_Q [NN * D];
__device__ float g_Rr[NN * D];
__device__ float g_Rc[NN * D];
// edge sort
__device__ int   g_cnt[NN];           // hist -> cursor
__device__ int   g_srow[NE];
__device__ int   g_scol[NE];
__device__ float g_sea[NE];
__device__ float g_sem[NE];
// fragment-permuted tf32 weights: 0 We2, 1 Wc2, 2 Wlin, 3 Wa1r, 4 Wa1c,
// 5 We1h, 6 Wn1, 7 Wn2, 8 Wc1r, 9 Wc1c
__device__ __align__(16) float g_Wp[10 * WSZ];

// fast silu: MUFU.EX2 + MUFU.RCP path
__device__ __forceinline__ float siluf(float v) {
    return __fdividef(v, 1.f + __expf(-v));
}

__device__ __forceinline__ u32 tf32r(float v) {
    u32 r;
    asm("cvt.rna.tf32.f32 %0, %1;" : "=r"(r) : "f"(v));
    return r;
}
__device__ __forceinline__ void mma8(float* c, uint4 a, uint2 b) {
    asm volatile(
        "mma.sync.aligned.m16n8k8.row.col.f32.tf32.tf32.f32 "
        "{%0,%1,%2,%3}, {%4,%5,%6,%7}, {%8,%9}, {%0,%1,%2,%3};"
        : "+f"(c[0]), "+f"(c[1]), "+f"(c[2]), "+f"(c[3])
        : "r"(a.x), "r"(a.y), "r"(a.z), "r"(a.w), "r"(b.x), "r"(b.y));
}
__device__ __forceinline__ void red2(float* p, float a, float b) {
    asm volatile("red.global.add.v2.f32 [%0], {%1, %2};"
                 :: "l"(p), "f"(a), "f"(b) : "memory");
}

// XOR-swizzled fragment stores
__device__ __forceinline__ void stp4(float* b0, float* b1, int e, int k0, float4 v) {
    float* base = (e & 16) ? b1 : b0;
    int s = k0 >> 3;
    int j0 = (e & 7) << 2;
    int pos = ((e & 8) >> 3) | ((k0 & 4) >> 1);
    int sw = s & 7;
    u32* row = (u32*)base + s * 128;
    row[(((j0 + 0) ^ sw) << 2) + pos] = tf32r(v.x);
    row[(((j0 + 1) ^ sw) << 2) + pos] = tf32r(v.y);
    row[(((j0 + 2) ^ sw) << 2) + pos] = tf32r(v.z);
    row[(((j0 + 3) ^ sw) << 2) + pos] = tf32r(v.w);
}
__device__ __forceinline__ void stp1(float* b0, float* b1, int e, int k, float v) {
    float* base = (e & 16) ? b1 : b0;
    int s = k >> 3;
    int j4 = ((e & 7) << 2) | (k & 3);
    int pos = ((e & 8) >> 3) | ((k & 4) >> 1);
    ((u32*)base)[s * 128 + (((j4 ^ (s & 7)) << 2) | pos)] = tf32r(v);
}

// ---------------- edge sort kernels ----------------
__global__ void zero_all() {
    int idx = blockIdx.x * blockDim.x + threadIdx.x;
    int stride = gridDim.x * blockDim.x;
    for (int i = idx; i < NN * D; i += stride) g_agg[i] = 0.f;
    for (int i = idx; i < NN * 3; i += stride) g_aggx[i] = 0.f;
    for (int i = idx; i < NN; i += stride) g_cnt[i] = 0;
}
__global__ void hist_rows(const int* __restrict__ ei) {
    int e = blockIdx.x * blockDim.x + threadIdx.x;
    if (e < NE) atomicAdd(&g_cnt[ei[e]], 1);
}
__global__ void scan_counts() {
    __shared__ int sh[1024];
    __shared__ int carry;
    int t = threadIdx.x;
    if (t == 0) carry = 0;
    __syncthreads();
    for (int base = 0; base < NN; base += 1024) {
        int v = (base + t < NN) ? g_cnt[base + t] : 0;
        sh[t] = v;
        __syncthreads();
        for (int o = 1; o < 1024; o <<= 1) {
            int u = (t >= o) ? sh[t - o] : 0;
            __syncthreads();
            sh[t] += u;
            __syncthreads();
        }
        int incl = sh[t];
        if (base + t < NN) g_cnt[base + t] = incl - v + carry;  // exclusive + carry
        __syncthreads();
        if (t == 1023) carry += incl;
        __syncthreads();
    }
}
__global__ void scatter_edges(const int* __restrict__ ei,
                              const float* __restrict__ edge_attr,
                              const float* __restrict__ edge_mask) {
    int e = blockIdx.x * blockDim.x + threadIdx.x;
    if (e >= NE) return;
    int r = ei[e];
    int pos = atomicAdd(&g_cnt[r], 1);
    g_srow[pos] = r;
    g_scol[pos] = ei[NE + e];
    g_sea[pos]  = edge_attr[e];
    g_sem[pos]  = edge_mask[e];
}

// ---------------- weight permute+tf32 prep (10 matrices of 128x128) --------------
__global__ void prep_weights(const float* __restrict__ We2, const float* __restrict__ Wc2,
                             const float* __restrict__ Wlin, const float* __restrict__ Wa1,
                             const float* __restrict__ We1, const float* __restrict__ Wn1,
                             const float* __restrict__ Wn2, const float* __restrict__ Wc1) {
    int m = blockIdx.y;
    const float* src;
    switch (m) {
        case 0: src = We2; break;
        case 1: src = Wc2; break;
        case 2: src = Wlin; break;
        case 3: src = Wa1; break;
        case 4: src = Wa1 + 128 * 128; break;
        case 5: src = We1; break;
        case 6: src = Wn1; break;
        case 7: src = Wn2; break;
        case 8: src = Wc1; break;
        default: src = Wc1 + 128 * 128; break;
    }
    float* dst = g_Wp + m * WSZ;
    int idx = blockIdx.x * blockDim.x + threadIdx.x;
    if (idx >= 16 * 16 * 32) return;
    int l = idx & 31, nt = (idx >> 5) & 15, s = idx >> 9;
    int k0 = s * 8 + (l & 3);
    int cc = nt * 8 + (l >> 2);
    u32* d = (u32*)(dst + (s * 16 + nt) * 64 + l * 2);
    d[0] = tf32r(src[k0 * 128 + cc]);
    d[1] = tf32r(src[(k0 + 4) * 128 + cc]);
}

// ---------------- tf32 GEMM mainloop ----------------
__device__ __forceinline__ void gemm16(const float* sA0, const float* sA1,
                                       const float* __restrict__ gW,
                                       int lane, int w, float (*c)[4]) {
#pragma unroll 2
    for (int s = 0; s < 16; s++) {
        int li = lane ^ (s & 7);
        uint4 a0 = ((const uint4*)sA0)[s * 32 + li];
        uint4 a1 = ((const uint4*)sA1)[s * 32 + li];
        uint2 b[4];
#pragma unroll
        for (int j = 0; j < 4; j++)
            b[j] = *(const uint2*)(gW + (s * 16 + w * 4 + j) * 64 + lane * 2);
#pragma unroll
        for (int j = 0; j < 4; j++) {
            mma8(c[j], a0, b[j]);
            mma8(c[4 + j], a1, b[j]);
        }
    }
}
__device__ __forceinline__ void init_bias(const float* __restrict__ bias,
                                          int lane, int w, float (*c)[4]) {
#pragma unroll
    for (int j = 0; j < 4; j++) {
        float2 bb = *(const float2*)(bias + w * 32 + j * 8 + (lane & 3) * 2);
        c[j][0] = bb.x; c[j][1] = bb.y; c[j][2] = bb.x; c[j][3] = bb.y;
        c[4 + j][0] = bb.x; c[4 + j][1] = bb.y; c[4 + j][2] = bb.x; c[4 + j][3] = bb.y;
    }
}
__device__ __forceinline__ void zero_c(float (*c)[4]) {
#pragma unroll
    for (int p = 0; p < 8; p++)
#pragma unroll
        for (int q = 0; q < 4; q++) c[p][q] = 0.f;
}
__device__ __forceinline__ void store_c_gmem(float (*c)[4], float* dst,
                                             int lane, int w) {
    int g = lane >> 2;
#pragma unroll
    for (int j = 0; j < 4; j++) {
        int n = w * 32 + j * 8 + (lane & 3) * 2;
#pragma unroll
        for (int m = 0; m < 2; m++) {
            int e = g + m * 16;
            *(float2*)(dst + e * D + n) = make_float2(c[m * 4 + j][0], c[m * 4 + j][1]);
            *(float2*)(dst + (e + 8) * D + n) = make_float2(c[m * 4 + j][2], c[m * 4 + j][3]);
        }
    }
}
__device__ __forceinline__ void frag_from_c(float (*c)[4], float* sF0, float* sF1,
                                            int lane, int w) {
    int g = lane >> 2;
#pragma unroll
    for (int j = 0; j < 4; j++) {
        int n = w * 32 + j * 8 + (lane & 3) * 2;
#pragma unroll
        for (int m = 0; m < 2; m++) {
            int e = g + m * 16;
            stp1(sF0, sF1, e, n, c[m * 4 + j][0]);
            stp1(sF0, sF1, e, n + 1, c[m * 4 + j][1]);
            stp1(sF0, sF1, e + 8, n, c[m * 4 + j][2]);
            stp1(sF0, sF1, e + 8, n + 1, c[m * 4 + j][3]);
        }
    }
}

// ---------------- node front: hh = h@Wlin+b; P_r, P_c, Q projections (mma) ------
__global__ void __launch_bounds__(128)
node_front(const float* __restrict__ h, const float* __restrict__ blin) {
    __shared__ __align__(16) float sF[2 * FR16];
    float* sF0 = sF;
    float* sF1 = sF + FR16;
    int t = threadIdx.x, lane = t & 31, w = t >> 5;
    int r0 = blockIdx.x * TN;
    int c4 = lane << 2;

#pragma unroll
    for (int i = 0; i < 8; i++) {
        int e = w * 8 + i;
        float4 hv = ((const float4*)(h + (r0 + e) * D))[lane];
        stp4(sF0, sF1, e, c4, hv);
    }
    __syncthreads();

    float c[8][4];
    init_bias(blin, lane, w, c);
    gemm16(sF0, sF1, g_Wp + 2 * WSZ, lane, w, c);
    __syncthreads();

    store_c_gmem(c, g_hh + r0 * D, lane, w);
    frag_from_c(c, sF0, sF1, lane, w);
    __syncthreads();

    float cp[8][4];
    zero_c(cp);
    gemm16(sF0, sF1, g_Wp + 3 * WSZ, lane, w, cp);
    store_c_gmem(cp, g_Pr + r0 * D, lane, w);
    zero_c(cp);
    gemm16(sF0, sF1, g_Wp + 4 * WSZ, lane, w, cp);
    store_c_gmem(cp, g_Pc + r0 * D, lane, w);
    zero_c(cp);
    gemm16(sF0, sF1, g_Wp + 5 * WSZ, lane, w, cp);
    store_c_gmem(cp, g_Q + r0 * D, lane, w);
}

// ---------------- edge message + attention (sorted edges, row-dedup) ------------
__global__ void __launch_bounds__(128, 5)
edge_msg(const float* __restrict__ x,
         const float* __restrict__ Wa1, const float* __restrict__ ba1,
         const float* __restrict__ Wa2, const float* __restrict__ ba2,
         const float* __restrict__ We1, const float* __restrict__ be1,
         const float* __restrict__ be2) {
    extern __shared__ float sm[];
    float* sA0   = sm;
    float* sA1   = sA0 + FR16;
    float* s_d   = sA1 + FR16;
    float* s_ea  = s_d + 32;
    float* s_z   = s_ea + 32;
    float* s_at  = s_z + 32;
    float* s_em  = s_at + 32;
    int*   s_row = (int*)(s_em + 32);
    int*   s_col = s_row + 32;

    int t = threadIdx.x, lane = t & 31, w = t >> 5;
    int e0b = blockIdx.x * TE;

    if (t < TE) {
        int e = t;
        int r = g_srow[e0b + e];
        int c = g_scol[e0b + e];
        s_row[e] = r;
        s_col[e] = c;
        s_em[e]  = g_sem[e0b + e];
        float ea = g_sea[e0b + e];
        s_ea[e]  = ea;
        float dx = x[r * 3 + 0] - x[c * 3 + 0];
        float dy = x[r * 3 + 1] - x[c * 3 + 1];
        float dz = x[r * 3 + 2] - x[c * 3 + 2];
        float dist = sqrtf(dx * dx + dy * dy + dz * dz + 1e-8f);
        s_d[e] = dist;
        g_e3[(e0b + e) * 3 + 0] = dist;
        g_e3[(e0b + e) * 3 + 1] = ea;
    }
    __syncthreads();

    {
        int c4 = lane << 2;
        float4 waD = *(const float4*)(Wa1 + 256 * 128 + c4);
        float4 waA = *(const float4*)(Wa1 + 257 * 128 + c4);
        float4 waG = *(const float4*)(Wa1 + 258 * 128 + c4);
        float4 bA  = *(const float4*)(ba1 + c4);
        float4 w2v = *(const float4*)(Wa2 + c4);
        float4 weD = *(const float4*)(We1 + 128 * 128 + c4);
        float4 weA = *(const float4*)(We1 + 129 * 128 + c4);
        float4 weG = *(const float4*)(We1 + 130 * 128 + c4);
        float4 bM  = *(const float4*)(be1 + c4);
        int prev_r = -1;
        float4 hr, pr, qr;
#pragma unroll
        for (int i = 0; i < 8; i++) {
            int e = w * 8 + i;
            int r = s_row[e], c = s_col[e];
            if (r != prev_r) {  // warp-uniform; sorted rows dedup
                hr = ((const float4*)(g_hh + r * D))[lane];
                pr = ((const float4*)(g_Pr + r * D))[lane];
                qr = ((const float4*)(g_Q + r * D))[lane];
                prev_r = r;
            }
            float4 hc = ((const float4*)(g_hh + c * D))[lane];
            float vx = hc.x - hr.x, vy = hc.y - hr.y;
            float vz = hc.z - hr.z, vw = hc.w - hr.w;
            float q = vx * vx + vy * vy + vz * vz + vw * vw;
#pragma unroll
            for (int o = 16; o > 0; o >>= 1) q += __shfl_xor_sync(0xffffffffu, q, o);
            float gg = sqrtf(q + 1e-8f);
            float dd = s_d[e], ea = s_ea[e];
            float4 pc = ((const float4*)(g_Pc + c * D))[lane];
            float4 qc = ((const float4*)(g_Q + c * D))[lane];
            float a0 = pr.x + pc.x + dd * waD.x + ea * waA.x + gg * waG.x + bA.x;
            float a1 = pr.y + pc.y + dd * waD.y + ea * waA.y + gg * waG.y + bA.y;
            float a2 = pr.z + pc.z + dd * waD.z + ea * waA.z + gg * waG.z + bA.z;
            float a3 = pr.w + pc.w + dd * waD.w + ea * waA.w + gg * waG.w + bA.w;
            float p = siluf(a0) * w2v.x + siluf(a1) * w2v.y +
                      siluf(a2) * w2v.z + siluf(a3) * w2v.w;
            float4 mv;
            mv.x = siluf(qc.x - qr.x + dd * weD.x + ea * weA.x + gg * weG.x + bM.x);
            mv.y = siluf(qc.y - qr.y + dd * weD.y + ea * weA.y + gg * weG.y + bM.y);
            mv.z = siluf(qc.z - qr.z + dd * weD.z + ea * weA.z + gg * weG.z + bM.z);
            mv.w = siluf(qc.w - qr.w + dd * weD.w + ea * weA.w + gg * weG.w + bM.w);
            stp4(sA0, sA1, e, c4, mv);
#pragma unroll
            for (int o = 16; o > 0; o >>= 1) p += __shfl_down_sync(0xffffffffu, p, o);
            if (lane == 0) {
                s_z[e] = p;
                g_e3[(e0b + e) * 3 + 2] = gg;
            }
        }
    }
    __syncthreads();
    if (t < TE) {
        float z = s_z[t] + ba2[0];
        s_at[t] = __fdividef(s_em[t], 1.f + __expf(-z));
    }
    __syncthreads();

    float cO[8][4];
    init_bias(be2, lane, w, cO);
    gemm16(sA0, sA1, g_Wp + 0 * WSZ, lane, w, cO);
#pragma unroll
    for (int j = 0; j < 4; j++) {
        int n = w * 32 + j * 8 + (lane & 3) * 2;
        int g = lane >> 2;
#pragma unroll
        for (int m = 0; m < 2; m++) {
            int e = g + m * 16;
            float aL = s_at[e], aH = s_at[e + 8];
            red2(&g_agg[s_row[e] * D + n], cO[m * 4 + j][0] * aL, cO[m * 4 + j][1] * aL);
            red2(&g_agg[s_row[e + 8] * D + n], cO[m * 4 + j][2] * aH, cO[m * 4 + j][3] * aH);
        }
    }
}

// ---------------- node MLP + residual + LN + silu -> d_out ; R projections ------
__global__ void __launch_bounds__(128)
node_mlp(const float* __restrict__ bn1, const float* __restrict__ bn2,
         const float* __restrict__ ln_g, const float* __restrict__ ln_b,
         float* __restrict__ out_h) {
    __shared__ __align__(16) float sF[2 * FR16];
    __shared__ float s_ps[TN * 4], s_pq[TN * 4], s_mu[TN], s_rs[TN];
    float* sF0 = sF;
    float* sF1 = sF + FR16;
    int t = threadIdx.x, lane = t & 31, w = t >> 5;
    int g = lane >> 2;
    int r0 = blockIdx.x * TN;
    int c4 = lane << 2;

#pragma unroll
    for (int i = 0; i < 8; i++) {
        int e = w * 8 + i;
        float4 av = ((const float4*)(g_agg + (r0 + e) * D))[lane];
        stp4(sF0, sF1, e, c4, av);
    }
    __syncthreads();

    float c1[8][4];
    init_bias(bn1, lane, w, c1);
    gemm16(sF0, sF1, g_Wp + 6 * WSZ, lane, w, c1);
    __syncthreads();

#pragma unroll
    for (int p = 0; p < 8; p++)
#pragma unroll
        for (int q = 0; q < 4; q++) c1[p][q] = siluf(c1[p][q]);
    frag_from_c(c1, sF0, sF1, lane, w);
    __syncthreads();

    float c2[8][4];
    init_bias(bn2, lane, w, c2);
    gemm16(sF0, sF1, g_Wp + 7 * WSZ, lane, w, c2);

#pragma unroll
    for (int j = 0; j < 4; j++) {
        int n = w * 32 + j * 8 + (lane & 3) * 2;
#pragma unroll
        for (int m = 0; m < 2; m++) {
            int e = g + m * 16;
            float2 h0 = *(const float2*)(g_hh + (r0 + e) * D + n);
            float2 h1 = *(const float2*)(g_hh + (r0 + e + 8) * D + n);
            c2[m * 4 + j][0] += h0.x;
            c2[m * 4 + j][1] += h0.y;
            c2[m * 4 + j][2] += h1.x;
            c2[m * 4 + j][3] += h1.y;
        }
    }

    {
        float su[4] = {0.f, 0.f, 0.f, 0.f};
        float sq[4] = {0.f, 0.f, 0.f, 0.f};
#pragma unroll
        for (int j = 0; j < 4; j++) {
#pragma unroll
            for (int m = 0; m < 2; m++) {
                float v0 = c2[m * 4 + j][0], v1 = c2[m * 4 + j][1];
                float v2 = c2[m * 4 + j][2], v3 = c2[m * 4 + j][3];
                su[m * 2 + 0] += v0 + v1;
                sq[m * 2 + 0] += v0 * v0 + v1 * v1;
                su[m * 2 + 1] += v2 + v3;
                sq[m * 2 + 1] += v2 * v2 + v3 * v3;
            }
        }
#pragma unroll
        for (int i = 0; i < 4; i++) {
            su[i] += __shfl_down_sync(0xffffffffu, su[i], 2, 4);
            su[i] += __shfl_down_sync(0xffffffffu, su[i], 1, 4);
            sq[i] += __shfl_down_sync(0xffffffffu, sq[i], 2, 4);
            sq[i] += __shfl_down_sync(0xffffffffu, sq[i], 1, 4);
        }
        if ((lane & 3) == 0) {
            s_ps[(g) * 4 + w]      = su[0];
            s_pq[(g) * 4 + w]      = sq[0];
            s_ps[(g + 8) * 4 + w]  = su[1];
            s_pq[(g + 8) * 4 + w]  = sq[1];
            s_ps[(g + 16) * 4 + w] = su[2];
            s_pq[(g + 16) * 4 + w] = sq[2];
            s_ps[(g + 24) * 4 + w] = su[3];
            s_pq[(g + 24) * 4 + w] = sq[3];
        }
    }
    __syncthreads();
    if (t < TN) {
        float s = s_ps[t * 4] + s_ps[t * 4 + 1] + s_ps[t * 4 + 2] + s_ps[t * 4 + 3];
        float q = s_pq[t * 4] + s_pq[t * 4 + 1] + s_pq[t * 4 + 2] + s_pq[t * 4 + 3];
        float mu = s * (1.f / 128.f);
        float var = q * (1.f / 128.f) - mu * mu;
        s_mu[t] = mu;
        s_rs[t] = rsqrtf(var + 1e-5f);
    }
    __syncthreads();

#pragma unroll
    for (int j = 0; j < 4; j++) {
        int n = w * 32 + j * 8 + (lane & 3) * 2;
        float2 gv = *(const float2*)(ln_g + n);
        float2 bv = *(const float2*)(ln_b + n);
#pragma unroll
        for (int m = 0; m < 2; m++) {
            int e = g + m * 16;
            float muL = s_mu[e], rsL = s_rs[e];
            float muH = s_mu[e + 8], rsH = s_rs[e + 8];
            float v0 = siluf((c2[m * 4 + j][0] - muL) * rsL * gv.x + bv.x);
            float v1 = siluf((c2[m * 4 + j][1] - muL) * rsL * gv.y + bv.y);
            float v2 = siluf((c2[m * 4 + j][2] - muH) * rsH * gv.x + bv.x);
            float v3 = siluf((c2[m * 4 + j][3] - muH) * rsH * gv.y + bv.y);
            *(float2*)(out_h + (r0 + e) * D + n) = make_float2(v0, v1);
            *(float2*)(out_h + (r0 + e + 8) * D + n) = make_float2(v2, v3);
            c2[m * 4 + j][0] = v0;
            c2[m * 4 + j][1] = v1;
            c2[m * 4 + j][2] = v2;
            c2[m * 4 + j][3] = v3;
        }
    }
    frag_from_c(c2, sF0, sF1, lane, w);
    __syncthreads();

    float cr[8][4];
    zero_c(cr);
    gemm16(sF0, sF1, g_Wp + 8 * WSZ, lane, w, cr);
    store_c_gmem(cr, g_Rr + r0 * D, lane, w);
    zero_c(cr);
    gemm16(sF0, sF1, g_Wp + 9 * WSZ, lane, w, cr);
    store_c_gmem(cr, g_Rc + r0 * D, lane, w);
}

// ---------------- coord MLP + scatter (sorted edges, row-dedup) ----------------
__global__ void __launch_bounds__(128, 6)
edge_coord(const float* __restrict__ x,
           const float* __restrict__ Wc1, const float* __restrict__ bc1,
           const float* __restrict__ bc2, const float* __restrict__ Wc3) {
    extern __shared__ float sm[];
    float* sA0   = sm;
    float* sA1   = sA0 + FR16;
    float* s_gp  = sA1 + FR16;
    float* s_d   = s_gp + 128;
    float* s_ea  = s_d + 32;
    float* s_geo = s_ea + 32;
    float* s_em  = s_geo + 32;
    int*   s_row = (int*)(s_em + 32);
    int*   s_col = s_row + 32;

    int t = threadIdx.x, lane = t & 31, w = t >> 5;
    int e0b = blockIdx.x * TE;

    if (t < TE) {
        s_row[t] = g_srow[e0b + t];
        s_col[t] = g_scol[e0b + t];
        s_em[t]  = g_sem[e0b + t];
        s_d[t]   = g_e3[(e0b + t) * 3 + 0];
        s_ea[t]  = g_e3[(e0b + t) * 3 + 1];
        s_geo[t] = g_e3[(e0b + t) * 3 + 2];
    }
    __syncthreads();

    {
        int c4 = lane << 2;
        float4 wcD = *(const float4*)(Wc1 + 256 * 128 + c4);
        float4 wcA = *(const float4*)(Wc1 + 257 * 128 + c4);
        float4 wcG = *(const float4*)(Wc1 + 258 * 128 + c4);
        float4 bC  = *(const float4*)(bc1 + c4);
        int prev_r = -1;
        float4 rr;
#pragma unroll
        for (int i = 0; i < 8; i++) {
            int e = w * 8 + i;
            int r = s_row[e], c = s_col[e];
            if (r != prev_r) {
                rr = ((const float4*)(g_Rr + r * D))[lane];
                prev_r = r;
            }
            float4 rc = ((const float4*)(g_Rc + c * D))[lane];
            float dd = s_d[e], ea = s_ea[e], gg = s_geo[e];
            float4 cv;
            cv.x = siluf(rr.x + rc.x + dd * wcD.x + ea * wcA.x + gg * wcG.x + bC.x);
            cv.y = siluf(rr.y + rc.y + dd * wcD.y + ea * wcA.y + gg * wcG.y + bC.y);
            cv.z = siluf(rr.z + rc.z + dd * wcD.z + ea * wcA.z + gg * wcG.z + bC.z);
            cv.w = siluf(rr.w + rc.w + dd * wcD.w + ea * wcA.w + gg * wcG.w + bC.w);
            stp4(sA0, sA1, e, c4, cv);
        }
    }
    __syncthreads();

    float c2[8][4];
    init_bias(bc2, lane, w, c2);
    gemm16(sA0, sA1, g_Wp + 1 * WSZ, lane, w, c2);

    {
        float p0 = 0.f, p1 = 0.f, p2 = 0.f, p3 = 0.f;
#pragma unroll
        for (int j = 0; j < 4; j++) {
            float2 w3 = *(const float2*)(Wc3 + w * 32 + j * 8 + (lane & 3) * 2);
            p0 += siluf(c2[j][0]) * w3.x + siluf(c2[j][1]) * w3.y;
            p1 += siluf(c2[j][2]) * w3.x + siluf(c2[j][3]) * w3.y;
            p2 += siluf(c2[4 + j][0]) * w3.x + siluf(c2[4 + j][1]) * w3.y;
            p3 += siluf(c2[4 + j][2]) * w3.x + siluf(c2[4 + j][3]) * w3.y;
        }
        p0 += __shfl_down_sync(0xffffffffu, p0, 2, 4); p0 += __shfl_down_sync(0xffffffffu, p0, 1, 4);
        p1 += __shfl_down_sync(0xffffffffu, p1, 2, 4); p1 += __shfl_down_sync(0xffffffffu, p1, 1, 4);
        p2 += __shfl_down_sync(0xffffffffu, p2, 2, 4); p2 += __shfl_down_sync(0xffffffffu, p2, 1, 4);
        p3 += __shfl_down_sync(0xffffffffu, p3, 2, 4); p3 += __shfl_down_sync(0xffffffffu, p3, 1, 4);
        if ((lane & 3) == 0) {
            int g = lane >> 2;
            s_gp[g * 4 + w]        = p0;
            s_gp[(g + 8) * 4 + w]  = p1;
            s_gp[(g + 16) * 4 + w] = p2;
            s_gp[(g + 24) * 4 + w] = p3;
        }
    }
    __syncthreads();

    if (t < TE) {
        int e = t;
        float mval = (s_gp[e * 4] + s_gp[e * 4 + 1] + s_gp[e * 4 + 2] + s_gp[e * 4 + 3])
                     * s_em[e];
        int r = s_row[e], c = s_col[e];
        float dx = x[r * 3 + 0] - x[c * 3 + 0];
        float dy = x[r * 3 + 1] - x[c * 3 + 1];
        float dz = x[r * 3 + 2] - x[c * 3 + 2];
        float inv = 1.f / (s_d[e] + 1.f);
        atomicAdd(&g_aggx[r * 3 + 0], dx * inv * mval);
        atomicAdd(&g_aggx[r * 3 + 1], dy * inv * mval);
        atomicAdd(&g_aggx[r * 3 + 2], dz * inv * mval);
    }
}

__global__ void finalize_x(const float* __restrict__ x,
                           const float* __restrict__ node_mask,
                           float* __restrict__ out) {
    int i = blockIdx.x * blockDim.x + threadIdx.x;
    if (i < NN * 3) {
        out[i] = (x[i] + g_aggx[i] * (1.f / 100.f)) * node_mask[i / 3];
    }
}

// ---------------- launcher ----------------
extern "C" void kernel_launch(void* const* d_in, const int* in_sizes, int n_in,
                              void* d_out, int out_size) {
    const float* h         = (const float*)d_in[0];
    const float* x         = (const float*)d_in[1];
    const int*   ei        = (const int*)d_in[2];
    const float* node_mask = (const float*)d_in[3];
    const float* edge_mask = (const float*)d_in[4];
    const float* edge_attr = (const float*)d_in[5];
    const float* Wlin = (const float*)d_in[6];
    const float* blin = (const float*)d_in[7];
    const float* We1  = (const float*)d_in[8];
    const float* be1  = (const float*)d_in[9];
    const float* We2  = (const float*)d_in[10];
    const float* be2  = (const float*)d_in[11];
    const float* Wn1  = (const float*)d_in[12];
    const float* bn1  = (const float*)d_in[13];
    const float* Wn2  = (const float*)d_in[14];
    const float* bn2  = (const float*)d_in[15];
    const float* Wa1  = (const float*)d_in[16];
    const float* ba1  = (const float*)d_in[17];
    const float* Wa2  = (const float*)d_in[18];
    const float* ba2  = (const float*)d_in[19];
    const float* ln_g = (const float*)d_in[20];
    const float* ln_b = (const float*)d_in[21];
    const float* Wc1  = (const float*)d_in[22];
    const float* bc1  = (const float*)d_in[23];
    const float* Wc2  = (const float*)d_in[24];
    const float* bc2  = (const float*)d_in[25];
    const float* Wc3  = (const float*)d_in[26];
    float* out = (float*)d_out;

    const int SMEM_MSG = (2 * FR16 + 5 * 32) * 4 + 2 * 32 * 4;
    const int SMEM_CRD = (2 * FR16 + 128 + 4 * 32) * 4 + 2 * 32 * 4;

    cudaFuncSetAttribute(edge_msg, cudaFuncAttributeMaxDynamicSharedMemorySize, SMEM_MSG);
    cudaFuncSetAttribute(edge_coord, cudaFuncAttributeMaxDynamicSharedMemorySize, SMEM_CRD);

    prep_weights<<<dim3(32, 10), 256>>>(We2, Wc2, Wlin, Wa1, We1, Wn1, Wn2, Wc1);
    zero_all<<<1024, 256>>>();
    hist_rows<<<(NE + 255) / 256, 256>>>(ei);
    scan_counts<<<1, 1024>>>();
    scatter_edges<<<(NE + 255) / 256, 256>>>(ei, edge_attr, edge_mask);
    node_front<<<NN / TN, 128>>>(h, blin);
    edge_msg<<<NE / TE, 128, SMEM_MSG>>>(x, Wa1, ba1, Wa2, ba2, We1, be1, be2);
    node_mlp<<<NN / TN, 128>>>(bn1, bn2, ln_g, ln_b, out);
    edge_coord<<<NE / TE, 128, SMEM_CRD>>>(x, Wc1, bc1, bc2, Wc3);
    finalize_x<<<(NN * 3 + 255) / 256, 256>>>(x, node_mask, out + NN * D);
}

// round 14
// speedup vs baseline: 1.5260x; 1.5260x over previous
#include <cuda_runtime.h>
#include <math.h>

#define NN 20000
#define NE 640000
#define D  128
#define TE 32
#define TN 32
#define FR16 2048  // fragment region: 16 ksteps * 128 words
#define WSZ 16384  // floats per permuted 128x128 weight

typedef unsigned int u32;

// ---------------- scratch (static device memory; no allocations) ----------------
__device__ float g_hh[NN * D];
__device__ float g_agg[NN * D];   // z = sum att*silu(M1)  (pre-We2 space)
__device__ float g_as[NN];        // sum att per row
__device__ float g_aggx[NN * 3];
__device__ float g_e3[NE * 3];
__device__ float g_Pr[NN * D];
__device__ float g_Pc[NN * D];
__device__ float g_Q [NN * D];
__device__ float g_Rr[NN * D];
__device__ float g_Rc[NN * D];
// fragment-permuted tf32 weights: 0 We2, 1 Wc2, 2 Wlin, 3 Wa1r, 4 Wa1c,
// 5 We1h, 6 Wn1, 7 Wn2, 8 Wc1r, 9 Wc1c
__device__ __align__(16) float g_Wp[10 * WSZ];

// fast silu: MUFU.EX2 + MUFU.RCP path
__device__ __forceinline__ float siluf(float v) {
    return __fdividef(v, 1.f + __expf(-v));
}

__device__ __forceinline__ u32 tf32r(float v) {
    u32 r;
    asm("cvt.rna.tf32.f32 %0, %1;" : "=r"(r) : "f"(v));
    return r;
}
__device__ __forceinline__ void mma8(float* c, uint4 a, uint2 b) {
    asm volatile(
        "mma.sync.aligned.m16n8k8.row.col.f32.tf32.tf32.f32 "
        "{%0,%1,%2,%3}, {%4,%5,%6,%7}, {%8,%9}, {%0,%1,%2,%3};"
        : "+f"(c[0]), "+f"(c[1]), "+f"(c[2]), "+f"(c[3])
        : "r"(a.x), "r"(a.y), "r"(a.z), "r"(a.w), "r"(b.x), "r"(b.y));
}
__device__ __forceinline__ void red4(float* p, float a, float b, float c, float d) {
    asm volatile("red.global.add.v4.f32 [%0], {%1, %2, %3, %4};"
                 :: "l"(p), "f"(a), "f"(b), "f"(c), "f"(d) : "memory");
}

// XOR-swizzled fragment stores
__device__ __forceinline__ void stp4(float* b0, float* b1, int e, int k0, float4 v) {
    float* base = (e & 16) ? b1 : b0;
    int s = k0 >> 3;
    int j0 = (e & 7) << 2;
    int pos = ((e & 8) >> 3) | ((k0 & 4) >> 1);
    int sw = s & 7;
    u32* row = (u32*)base + s * 128;
    row[(((j0 + 0) ^ sw) << 2) + pos] = tf32r(v.x);
    row[(((j0 + 1) ^ sw) << 2) + pos] = tf32r(v.y);
    row[(((j0 + 2) ^ sw) << 2) + pos] = tf32r(v.z);
    row[(((j0 + 3) ^ sw) << 2) + pos] = tf32r(v.w);
}
__device__ __forceinline__ void stp1(float* b0, float* b1, int e, int k, float v) {
    float* base = (e & 16) ? b1 : b0;
    int s = k >> 3;
    int j4 = ((e & 7) << 2) | (k & 3);
    int pos = ((e & 8) >> 3) | ((k & 4) >> 1);
    ((u32*)base)[s * 128 + (((j4 ^ (s & 7)) << 2) | pos)] = tf32r(v);
}

// ---------------- weight permute+tf32 prep ----------------
__global__ void prep_weights(const float* __restrict__ We2, const float* __restrict__ Wc2,
                             const float* __restrict__ Wlin, const float* __restrict__ Wa1,
                             const float* __restrict__ We1, const float* __restrict__ Wn1,
                             const float* __restrict__ Wn2, const float* __restrict__ Wc1) {
    int m = blockIdx.y;
    const float* src;
    switch (m) {
        case 0: src = We2; break;
        case 1: src = Wc2; break;
        case 2: src = Wlin; break;
        case 3: src = Wa1; break;
        case 4: src = Wa1 + 128 * 128; break;
        case 5: src = We1; break;
        case 6: src = Wn1; break;
        case 7: src = Wn2; break;
        case 8: src = Wc1; break;
        default: src = Wc1 + 128 * 128; break;
    }
    float* dst = g_Wp + m * WSZ;
    int idx = blockIdx.x * blockDim.x + threadIdx.x;
    if (idx >= 16 * 16 * 32) return;
    int l = idx & 31, nt = (idx >> 5) & 15, s = idx >> 9;
    int k0 = s * 8 + (l & 3);
    int cc = nt * 8 + (l >> 2);
    u32* d = (u32*)(dst + (s * 16 + nt) * 64 + l * 2);
    d[0] = tf32r(src[k0 * 128 + cc]);
    d[1] = tf32r(src[(k0 + 4) * 128 + cc]);
}

__global__ void zero_all() {
    int idx = blockIdx.x * blockDim.x + threadIdx.x;
    int stride = gridDim.x * blockDim.x;
    for (int i = idx; i < NN * D; i += stride) g_agg[i] = 0.f;
    for (int i = idx; i < NN * 3; i += stride) g_aggx[i] = 0.f;
    for (int i = idx; i < NN; i += stride) g_as[i] = 0.f;
}

// ---------------- tf32 GEMM mainloop ----------------
__device__ __forceinline__ void gemm16(const float* sA0, const float* sA1,
                                       const float* __restrict__ gW,
                                       int lane, int w, float (*c)[4]) {
#pragma unroll 2
    for (int s = 0; s < 16; s++) {
        int li = lane ^ (s & 7);
        uint4 a0 = ((const uint4*)sA0)[s * 32 + li];
        uint4 a1 = ((const uint4*)sA1)[s * 32 + li];
        uint2 b[4];
#pragma unroll
        for (int j = 0; j < 4; j++)
            b[j] = *(const uint2*)(gW + (s * 16 + w * 4 + j) * 64 + lane * 2);
#pragma unroll
        for (int j = 0; j < 4; j++) {
            mma8(c[j], a0, b[j]);
            mma8(c[4 + j], a1, b[j]);
        }
    }
}
__device__ __forceinline__ void init_bias(const float* __restrict__ bias,
                                          int lane, int w, float (*c)[4]) {
#pragma unroll
    for (int j = 0; j < 4; j++) {
        float2 bb = *(const float2*)(bias + w * 32 + j * 8 + (lane & 3) * 2);
        c[j][0] = bb.x; c[j][1] = bb.y; c[j][2] = bb.x; c[j][3] = bb.y;
        c[4 + j][0] = bb.x; c[4 + j][1] = bb.y; c[4 + j][2] = bb.x; c[4 + j][3] = bb.y;
    }
}
__device__ __forceinline__ void zero_c(float (*c)[4]) {
#pragma unroll
    for (int p = 0; p < 8; p++)
#pragma unroll
        for (int q = 0; q < 4; q++) c[p][q] = 0.f;
}
__device__ __forceinline__ void store_c_gmem(float (*c)[4], float* dst,
                                             int lane, int w) {
    int g = lane >> 2;
#pragma unroll
    for (int j = 0; j < 4; j++) {
        int n = w * 32 + j * 8 + (lane & 3) * 2;
#pragma unroll
        for (int m = 0; m < 2; m++) {
            int e = g + m * 16;
            *(float2*)(dst + e * D + n) = make_float2(c[m * 4 + j][0], c[m * 4 + j][1]);
            *(float2*)(dst + (e + 8) * D + n) = make_float2(c[m * 4 + j][2], c[m * 4 + j][3]);
        }
    }
}
__device__ __forceinline__ void frag_from_c(float (*c)[4], float* sF0, float* sF1,
                                            int lane, int w) {
    int g = lane >> 2;
#pragma unroll
    for (int j = 0; j < 4; j++) {
        int n = w * 32 + j * 8 + (lane & 3) * 2;
#pragma unroll
        for (int m = 0; m < 2; m++) {
            int e = g + m * 16;
            stp1(sF0, sF1, e, n, c[m * 4 + j][0]);
            stp1(sF0, sF1, e, n + 1, c[m * 4 + j][1]);
            stp1(sF0, sF1, e + 8, n, c[m * 4 + j][2]);
            stp1(sF0, sF1, e + 8, n + 1, c[m * 4 + j][3]);
        }
    }
}

// ---------------- node front: hh = h@Wlin+b; P_r, P_c, Q projections (mma) ------
__global__ void __launch_bounds__(128)
node_front(const float* __restrict__ h, const float* __restrict__ blin) {
    __shared__ __align__(16) float sF[2 * FR16];
    float* sF0 = sF;
    float* sF1 = sF + FR16;
    int t = threadIdx.x, lane = t & 31, w = t >> 5;
    int r0 = blockIdx.x * TN;
    int c4 = lane << 2;

#pragma unroll
    for (int i = 0; i < 8; i++) {
        int e = w * 8 + i;
        float4 hv = ((const float4*)(h + (r0 + e) * D))[lane];
        stp4(sF0, sF1, e, c4, hv);
    }
    __syncthreads();

    float c[8][4];
    init_bias(blin, lane, w, c);
    gemm16(sF0, sF1, g_Wp + 2 * WSZ, lane, w, c);
    __syncthreads();

    store_c_gmem(c, g_hh + r0 * D, lane, w);
    frag_from_c(c, sF0, sF1, lane, w);
    __syncthreads();

    float cp[8][4];
    zero_c(cp);
    gemm16(sF0, sF1, g_Wp + 3 * WSZ, lane, w, cp);
    store_c_gmem(cp, g_Pr + r0 * D, lane, w);
    zero_c(cp);
    gemm16(sF0, sF1, g_Wp + 4 * WSZ, lane, w, cp);
    store_c_gmem(cp, g_Pc + r0 * D, lane, w);
    zero_c(cp);
    gemm16(sF0, sF1, g_Wp + 5 * WSZ, lane, w, cp);
    store_c_gmem(cp, g_Q + r0 * D, lane, w);
}

// ---------------- edge message + attention (no MMA: We2 hoisted to nodes) -------
__global__ void __launch_bounds__(128, 6)
edge_msg(const float* __restrict__ x, const int* __restrict__ ei,
         const float* __restrict__ edge_mask,
         const float* __restrict__ edge_attr,
         const float* __restrict__ Wa1, const float* __restrict__ ba1,
         const float* __restrict__ Wa2, const float* __restrict__ ba2,
         const float* __restrict__ We1, const float* __restrict__ be1) {
    __shared__ float s_d[32], s_ea[32], s_em[32];
    __shared__ int s_row[32], s_col[32];

    int t = threadIdx.x, lane = t & 31, w = t >> 5;
    int e0b = blockIdx.x * TE;

    if (t < TE) {
        int e = t;
        int r = ei[e0b + e];
        int c = ei[NE + e0b + e];
        s_row[e] = r;
        s_col[e] = c;
        s_em[e]  = edge_mask[e0b + e];
        float ea = edge_attr[e0b + e];
        s_ea[e]  = ea;
        float dx = x[r * 3 + 0] - x[c * 3 + 0];
        float dy = x[r * 3 + 1] - x[c * 3 + 1];
        float dz = x[r * 3 + 2] - x[c * 3 + 2];
        float dist = sqrtf(dx * dx + dy * dy + dz * dz + 1e-8f);
        s_d[e] = dist;
        g_e3[(e0b + e) * 3 + 0] = dist;
        g_e3[(e0b + e) * 3 + 1] = ea;
    }
    __syncthreads();

    {
        int c4 = lane << 2;
        float4 waD = *(const float4*)(Wa1 + 256 * 128 + c4);
        float4 waA = *(const float4*)(Wa1 + 257 * 128 + c4);
        float4 waG = *(const float4*)(Wa1 + 258 * 128 + c4);
        float4 bA  = *(const float4*)(ba1 + c4);
        float4 w2v = *(const float4*)(Wa2 + c4);
        float4 weD = *(const float4*)(We1 + 128 * 128 + c4);
        float4 weA = *(const float4*)(We1 + 129 * 128 + c4);
        float4 weG = *(const float4*)(We1 + 130 * 128 + c4);
        float4 bM  = *(const float4*)(be1 + c4);
        float b2 = ba2[0];
#pragma unroll
        for (int i = 0; i < 8; i++) {
            int e = w * 8 + i;
            int r = s_row[e], c = s_col[e];
            float4 hr = ((const float4*)(g_hh + r * D))[lane];
            float4 hc = ((const float4*)(g_hh + c * D))[lane];
            float vx = hc.x - hr.x, vy = hc.y - hr.y;
            float vz = hc.z - hr.z, vw = hc.w - hr.w;
            float q = vx * vx + vy * vy + vz * vz + vw * vw;
#pragma unroll
            for (int o = 16; o > 0; o >>= 1) q += __shfl_xor_sync(0xffffffffu, q, o);
            float gg = sqrtf(q + 1e-8f);
            float dd = s_d[e], ea = s_ea[e];
            float4 pr = ((const float4*)(g_Pr + r * D))[lane];
            float4 pc = ((const float4*)(g_Pc + c * D))[lane];
            float4 qr = ((const float4*)(g_Q + r * D))[lane];
            float4 qc = ((const float4*)(g_Q + c * D))[lane];
            float a0 = pr.x + pc.x + dd * waD.x + ea * waA.x + gg * waG.x + bA.x;
            float a1 = pr.y + pc.y + dd * waD.y + ea * waA.y + gg * waG.y + bA.y;
            float a2 = pr.z + pc.z + dd * waD.z + ea * waA.z + gg * waG.z + bA.z;
            float a3 = pr.w + pc.w + dd * waD.w + ea * waA.w + gg * waG.w + bA.w;
            float p = siluf(a0) * w2v.x + siluf(a1) * w2v.y +
                      siluf(a2) * w2v.z + siluf(a3) * w2v.w;
#pragma unroll
            for (int o = 16; o > 0; o >>= 1) p += __shfl_xor_sync(0xffffffffu, p, o);
            float att = __fdividef(s_em[e], 1.f + __expf(-(p + b2)));
            float m0 = siluf(qc.x - qr.x + dd * weD.x + ea * weA.x + gg * weG.x + bM.x) * att;
            float m1 = siluf(qc.y - qr.y + dd * weD.y + ea * weA.y + gg * weG.y + bM.y) * att;
            float m2 = siluf(qc.z - qr.z + dd * weD.z + ea * weA.z + gg * weG.z + bM.z) * att;
            float m3 = siluf(qc.w - qr.w + dd * weD.w + ea * weA.w + gg * weG.w + bM.w) * att;
            red4(&g_agg[r * D + c4], m0, m1, m2, m3);
            if (lane == 0) {
                atomicAdd(&g_as[r], att);
                g_e3[(e0b + e) * 3 + 2] = gg;
            }
        }
    }
}

// ---------------- node MLP: We2 stage + residual + LN + silu ; R projections ----
__global__ void __launch_bounds__(128)
node_mlp(const float* __restrict__ be2,
         const float* __restrict__ bn1, const float* __restrict__ bn2,
         const float* __restrict__ ln_g, const float* __restrict__ ln_b,
         float* __restrict__ out_h) {
    __shared__ __align__(16) float sF[2 * FR16];
    __shared__ float s_ps[TN * 4], s_pq[TN * 4], s_mu[TN], s_rs[TN], s_as[TN];
    float* sF0 = sF;
    float* sF1 = sF + FR16;
    int t = threadIdx.x, lane = t & 31, w = t >> 5;
    int g = lane >> 2;
    int r0 = blockIdx.x * TN;
    int c4 = lane << 2;

    if (t < TN) s_as[t] = g_as[r0 + t];
#pragma unroll
    for (int i = 0; i < 8; i++) {
        int e = w * 8 + i;
        float4 zv = ((const float4*)(g_agg + (r0 + e) * D))[lane];
        stp4(sF0, sF1, e, c4, zv);
    }
    __syncthreads();

    // agg = z @ We2 + be2 * sum_att
    float c0[8][4];
    zero_c(c0);
    gemm16(sF0, sF1, g_Wp + 0 * WSZ, lane, w, c0);
    __syncthreads();
#pragma unroll
    for (int j = 0; j < 4; j++) {
        int n = w * 32 + j * 8 + (lane & 3) * 2;
        float2 bv = *(const float2*)(be2 + n);
#pragma unroll
        for (int m = 0; m < 2; m++) {
            int e = g + m * 16;
            float aL = s_as[e], aH = s_as[e + 8];
            c0[m * 4 + j][0] += bv.x * aL;
            c0[m * 4 + j][1] += bv.y * aL;
            c0[m * 4 + j][2] += bv.x * aH;
            c0[m * 4 + j][3] += bv.y * aH;
        }
    }
    frag_from_c(c0, sF0, sF1, lane, w);
    __syncthreads();

    float c1[8][4];
    init_bias(bn1, lane, w, c1);
    gemm16(sF0, sF1, g_Wp + 6 * WSZ, lane, w, c1);
    __syncthreads();

#pragma unroll
    for (int p = 0; p < 8; p++)
#pragma unroll
        for (int q = 0; q < 4; q++) c1[p][q] = siluf(c1[p][q]);
    frag_from_c(c1, sF0, sF1, lane, w);
    __syncthreads();

    float c2[8][4];
    init_bias(bn2, lane, w, c2);
    gemm16(sF0, sF1, g_Wp + 7 * WSZ, lane, w, c2);

#pragma unroll
    for (int j = 0; j < 4; j++) {
        int n = w * 32 + j * 8 + (lane & 3) * 2;
#pragma unroll
        for (int m = 0; m < 2; m++) {
            int e = g + m * 16;
            float2 h0 = *(const float2*)(g_hh + (r0 + e) * D + n);
            float2 h1 = *(const float2*)(g_hh + (r0 + e + 8) * D + n);
            c2[m * 4 + j][0] += h0.x;
            c2[m * 4 + j][1] += h0.y;
            c2[m * 4 + j][2] += h1.x;
            c2[m * 4 + j][3] += h1.y;
        }
    }

    {
        float su[4] = {0.f, 0.f, 0.f, 0.f};
        float sq[4] = {0.f, 0.f, 0.f, 0.f};
#pragma unroll
        for (int j = 0; j < 4; j++) {
#pragma unroll
            for (int m = 0; m < 2; m++) {
                float v0 = c2[m * 4 + j][0], v1 = c2[m * 4 + j][1];
                float v2 = c2[m * 4 + j][2], v3 = c2[m * 4 + j][3];
                su[m * 2 + 0] += v0 + v1;
                sq[m * 2 + 0] += v0 * v0 + v1 * v1;
                su[m * 2 + 1] += v2 + v3;
                sq[m * 2 + 1] += v2 * v2 + v3 * v3;
            }
        }
#pragma unroll
        for (int i = 0; i < 4; i++) {
            su[i] += __shfl_down_sync(0xffffffffu, su[i], 2, 4);
            su[i] += __shfl_down_sync(0xffffffffu, su[i], 1, 4);
            sq[i] += __shfl_down_sync(0xffffffffu, sq[i], 2, 4);
            sq[i] += __shfl_down_sync(0xffffffffu, sq[i], 1, 4);
        }
        if ((lane & 3) == 0) {
            s_ps[(g) * 4 + w]      = su[0];
            s_pq[(g) * 4 + w]      = sq[0];
            s_ps[(g + 8) * 4 + w]  = su[1];
            s_pq[(g + 8) * 4 + w]  = sq[1];
            s_ps[(g + 16) * 4 + w] = su[2];
            s_pq[(g + 16) * 4 + w] = sq[2];
            s_ps[(g + 24) * 4 + w] = su[3];
            s_pq[(g + 24) * 4 + w] = sq[3];
        }
    }
    __syncthreads();
    if (t < TN) {
        float s = s_ps[t * 4] + s_ps[t * 4 + 1] + s_ps[t * 4 + 2] + s_ps[t * 4 + 3];
        float q = s_pq[t * 4] + s_pq[t * 4 + 1] + s_pq[t * 4 + 2] + s_pq[t * 4 + 3];
        float mu = s * (1.f / 128.f);
        float var = q * (1.f / 128.f) - mu * mu;
        s_mu[t] = mu;
        s_rs[t] = rsqrtf(var + 1e-5f);
    }
    __syncthreads();

#pragma unroll
    for (int j = 0; j < 4; j++) {
        int n = w * 32 + j * 8 + (lane & 3) * 2;
        float2 gv = *(const float2*)(ln_g + n);
        float2 bv = *(const float2*)(ln_b + n);
#pragma unroll
        for (int m = 0; m < 2; m++) {
            int e = g + m * 16;
            float muL = s_mu[e], rsL = s_rs[e];
            float muH = s_mu[e + 8], rsH = s_rs[e + 8];
            float v0 = siluf((c2[m * 4 + j][0] - muL) * rsL * gv.x + bv.x);
            float v1 = siluf((c2[m * 4 + j][1] - muL) * rsL * gv.y + bv.y);
            float v2 = siluf((c2[m * 4 + j][2] - muH) * rsH * gv.x + bv.x);
            float v3 = siluf((c2[m * 4 + j][3] - muH) * rsH * gv.y + bv.y);
            *(float2*)(out_h + (r0 + e) * D + n) = make_float2(v0, v1);
            *(float2*)(out_h + (r0 + e + 8) * D + n) = make_float2(v2, v3);
            c2[m * 4 + j][0] = v0;
            c2[m * 4 + j][1] = v1;
            c2[m * 4 + j][2] = v2;
            c2[m * 4 + j][3] = v3;
        }
    }
    frag_from_c(c2, sF0, sF1, lane, w);
    __syncthreads();

    float cr[8][4];
    zero_c(cr);
    gemm16(sF0, sF1, g_Wp + 8 * WSZ, lane, w, cr);
    store_c_gmem(cr, g_Rr + r0 * D, lane, w);
    zero_c(cr);
    gemm16(sF0, sF1, g_Wp + 9 * WSZ, lane, w, cr);
    store_c_gmem(cr, g_Rc + r0 * D, lane, w);
}

// ---------------- coord MLP + scatter (R12 form) ----------------
__global__ void __launch_bounds__(128, 6)
edge_coord(const float* __restrict__ x, const int* __restrict__ ei,
           const float* __restrict__ edge_mask,
           const float* __restrict__ Wc1, const float* __restrict__ bc1,
           const float* __restrict__ bc2, const float* __restrict__ Wc3) {
    extern __shared__ float sm[];
    float* sA0   = sm;
    float* sA1   = sA0 + FR16;
    float* s_gp  = sA1 + FR16;
    float* s_d   = s_gp + 128;
    float* s_ea  = s_d + 32;
    float* s_geo = s_ea + 32;
    float* s_em  = s_geo + 32;
    int*   s_row = (int*)(s_em + 32);
    int*   s_col = s_row + 32;

    int t = threadIdx.x, lane = t & 31, w = t >> 5;
    int e0b = blockIdx.x * TE;

    if (t < TE) {
        s_row[t] = ei[e0b + t];
        s_col[t] = ei[NE + e0b + t];
        s_em[t]  = edge_mask[e0b + t];
        s_d[t]   = g_e3[(e0b + t) * 3 + 0];
        s_ea[t]  = g_e3[(e0b + t) * 3 + 1];
        s_geo[t] = g_e3[(e0b + t) * 3 + 2];
    }
    __syncthreads();

    {
        int c4 = lane << 2;
        float4 wcD = *(const float4*)(Wc1 + 256 * 128 + c4);
        float4 wcA = *(const float4*)(Wc1 + 257 * 128 + c4);
        float4 wcG = *(const float4*)(Wc1 + 258 * 128 + c4);
        float4 bC  = *(const float4*)(bc1 + c4);
#pragma unroll
        for (int i = 0; i < 8; i++) {
            int e = w * 8 + i;
            int r = s_row[e], c = s_col[e];
            float4 rr = ((const float4*)(g_Rr + r * D))[lane];
            float4 rc = ((const float4*)(g_Rc + c * D))[lane];
            float dd = s_d[e], ea = s_ea[e], gg = s_geo[e];
            float4 cv;
            cv.x = siluf(rr.x + rc.x + dd * wcD.x + ea * wcA.x + gg * wcG.x + bC.x);
            cv.y = siluf(rr.y + rc.y + dd * wcD.y + ea * wcA.y + gg * wcG.y + bC.y);
            cv.z = siluf(rr.z + rc.z + dd * wcD.z + ea * wcA.z + gg * wcG.z + bC.z);
            cv.w = siluf(rr.w + rc.w + dd * wcD.w + ea * wcA.w + gg * wcG.w + bC.w);
            stp4(sA0, sA1, e, c4, cv);
        }
    }
    __syncthreads();

    float c2[8][4];
    init_bias(bc2, lane, w, c2);
    gemm16(sA0, sA1, g_Wp + 1 * WSZ, lane, w, c2);

    {
        float p0 = 0.f, p1 = 0.f, p2 = 0.f, p3 = 0.f;
#pragma unroll
        for (int j = 0; j < 4; j++) {
            float2 w3 = *(const float2*)(Wc3 + w * 32 + j * 8 + (lane & 3) * 2);
            p0 += siluf(c2[j][0]) * w3.x + siluf(c2[j][1]) * w3.y;
            p1 += siluf(c2[j][2]) * w3.x + siluf(c2[j][3]) * w3.y;
            p2 += siluf(c2[4 + j][0]) * w3.x + siluf(c2[4 + j][1]) * w3.y;
            p3 += siluf(c2[4 + j][2]) * w3.x + siluf(c2[4 + j][3]) * w3.y;
        }
        p0 += __shfl_down_sync(0xffffffffu, p0, 2, 4); p0 += __shfl_down_sync(0xffffffffu, p0, 1, 4);
        p1 += __shfl_down_sync(0xffffffffu, p1, 2, 4); p1 += __shfl_down_sync(0xffffffffu, p1, 1, 4);
        p2 += __shfl_down_sync(0xffffffffu, p2, 2, 4); p2 += __shfl_down_sync(0xffffffffu, p2, 1, 4);
        p3 += __shfl_down_sync(0xffffffffu, p3, 2, 4); p3 += __shfl_down_sync(0xffffffffu, p3, 1, 4);
        if ((lane & 3) == 0) {
            int g = lane >> 2;
            s_gp[g * 4 + w]        = p0;
            s_gp[(g + 8) * 4 + w]  = p1;
            s_gp[(g + 16) * 4 + w] = p2;
            s_gp[(g + 24) * 4 + w] = p3;
        }
    }
    __syncthreads();

    if (t < TE) {
        int e = t;
        float mval = (s_gp[e * 4] + s_gp[e * 4 + 1] + s_gp[e * 4 + 2] + s_gp[e * 4 + 3])
                     * s_em[e];
        int r = s_row[e], c = s_col[e];
        float dx = x[r * 3 + 0] - x[c * 3 + 0];
        float dy = x[r * 3 + 1] - x[c * 3 + 1];
        float dz = x[r * 3 + 2] - x[c * 3 + 2];
        float inv = 1.f / (s_d[e] + 1.f);
        atomicAdd(&g_aggx[r * 3 + 0], dx * inv * mval);
        atomicAdd(&g_aggx[r * 3 + 1], dy * inv * mval);
        atomicAdd(&g_aggx[r * 3 + 2], dz * inv * mval);
    }
}

__global__ void finalize_x(const float* __restrict__ x,
                           const float* __restrict__ node_mask,
                           float* __restrict__ out) {
    int i = blockIdx.x * blockDim.x + threadIdx.x;
    if (i < NN * 3) {
        out[i] = (x[i] + g_aggx[i] * (1.f / 100.f)) * node_mask[i / 3];
    }
}

// ---------------- launcher ----------------
extern "C" void kernel_launch(void* const* d_in, const int* in_sizes, int n_in,
                              void* d_out, int out_size) {
    const float* h         = (const float*)d_in[0];
    const float* x         = (const float*)d_in[1];
    const int*   ei        = (const int*)d_in[2];
    const float* node_mask = (const float*)d_in[3];
    const float* edge_mask = (const float*)d_in[4];
    const float* edge_attr = (const float*)d_in[5];
    const float* Wlin = (const float*)d_in[6];
    const float* blin = (const float*)d_in[7];
    const float* We1  = (const float*)d_in[8];
    const float* be1  = (const float*)d_in[9];
    const float* We2  = (const float*)d_in[10];
    const float* be2  = (const float*)d_in[11];
    const float* Wn1  = (const float*)d_in[12];
    const float* bn1  = (const float*)d_in[13];
    const float* Wn2  = (const float*)d_in[14];
    const float* bn2  = (const float*)d_in[15];
    const float* Wa1  = (const float*)d_in[16];
    const float* ba1  = (const float*)d_in[17];
    const float* Wa2  = (const float*)d_in[18];
    const float* ba2  = (const float*)d_in[19];
    const float* ln_g = (const float*)d_in[20];
    const float* ln_b = (const float*)d_in[21];
    const float* Wc1  = (const float*)d_in[22];
    const float* bc1  = (const float*)d_in[23];
    const float* Wc2  = (const float*)d_in[24];
    const float* bc2  = (const float*)d_in[25];
    const float* Wc3  = (const float*)d_in[26];
    float* out = (float*)d_out;

    const int SMEM_CRD = (2 * FR16 + 128 + 4 * 32) * 4 + 2 * 32 * 4;
    cudaFuncSetAttribute(edge_coord, cudaFuncAttributeMaxDynamicSharedMemorySize, SMEM_CRD);

    prep_weights<<<dim3(32, 10), 256>>>(We2, Wc2, Wlin, Wa1, We1, Wn1, Wn2, Wc1);
    zero_all<<<1024, 256>>>();
    node_front<<<NN / TN, 128>>>(h, blin);
    edge_msg<<<NE / TE, 128>>>(x, ei, edge_mask, edge_attr,
                               Wa1, ba1, Wa2, ba2, We1, be1);
    node_mlp<<<NN / TN, 128>>>(be2, bn1, bn2, ln_g, ln_b, out);
    edge_coord<<<NE / TE, 128, SMEM_CRD>>>(x, ei, edge_mask, Wc1, bc1, bc2, Wc3);
    finalize_x<<<(NN * 3 + 255) / 256, 256>>>(x, node_mask, out + NN * D);
}

// round 15
// speedup vs baseline: 1.5338x; 1.0051x over previous
#include <cuda_runtime.h>
#include <math.h>

#define NN 20000
#define NE 640000
#define D  128
#define TE 32
#define TN 32
#define FR16 2048  // fragment region: 16 ksteps * 128 words
#define WSZ 16384  // floats per permuted 128x128 weight

typedef unsigned int u32;

// ---------------- scratch (static device memory; no allocations) ----------------
__device__ float g_hh[NN * D];
__device__ float g_agg[NN * D];   // z = sum att*silu(M1)  (pre-We2 space)
__device__ float g_as[NN];        // sum att per row
__device__ float g_aggx[NN * 3];
__device__ float g_e3[NE * 3];
__device__ float g_Pr[NN * D];
__device__ float g_Pc[NN * D];
__device__ float g_Q [NN * D];
__device__ float g_Rr[NN * D];
__device__ float g_Rc[NN * D];
// fragment-permuted tf32 weights: 0 We2, 1 Wc2, 2 Wlin, 3 Wa1r, 4 Wa1c,
// 5 We1h, 6 Wn1, 7 Wn2, 8 Wc1r, 9 Wc1c
__device__ __align__(16) float g_Wp[10 * WSZ];

// fast silu
__device__ __forceinline__ float siluf(float v) {
    return __fdividef(v, 1.f + __expf(-v));
}

__device__ __forceinline__ u32 tf32r(float v) {
    u32 r;
    asm("cvt.rna.tf32.f32 %0, %1;" : "=r"(r) : "f"(v));
    return r;
}
__device__ __forceinline__ void mma8(float* c, uint4 a, uint2 b) {
    asm volatile(
        "mma.sync.aligned.m16n8k8.row.col.f32.tf32.tf32.f32 "
        "{%0,%1,%2,%3}, {%4,%5,%6,%7}, {%8,%9}, {%0,%1,%2,%3};"
        : "+f"(c[0]), "+f"(c[1]), "+f"(c[2]), "+f"(c[3])
        : "r"(a.x), "r"(a.y), "r"(a.z), "r"(a.w), "r"(b.x), "r"(b.y));
}
__device__ __forceinline__ void red4(float* p, float a, float b, float c, float d) {
    asm volatile("red.global.add.v4.f32 [%0], {%1, %2, %3, %4};"
                 :: "l"(p), "f"(a), "f"(b), "f"(c), "f"(d) : "memory");
}
// weight load: keep resident in L1 across blocks
__device__ __forceinline__ uint2 ldg_w(const float* p) {
    uint2 v;
    asm("ld.global.L1::evict_last.v2.u32 {%0,%1}, [%2];"
        : "=r"(v.x), "=r"(v.y) : "l"(p));
    return v;
}
// streaming gather load: evict first, don't thrash weights
__device__ __forceinline__ float4 ldg_s(const float* p) {
    float4 v;
    asm("ld.global.L1::evict_first.v4.f32 {%0,%1,%2,%3}, [%4];"
        : "=f"(v.x), "=f"(v.y), "=f"(v.z), "=f"(v.w) : "l"(p));
    return v;
}

// XOR-swizzled fragment stores
__device__ __forceinline__ void stp4(float* b0, float* b1, int e, int k0, float4 v) {
    float* base = (e & 16) ? b1 : b0;
    int s = k0 >> 3;
    int j0 = (e & 7) << 2;
    int pos = ((e & 8) >> 3) | ((k0 & 4) >> 1);
    int sw = s & 7;
    u32* row = (u32*)base + s * 128;
    row[(((j0 + 0) ^ sw) << 2) + pos] = tf32r(v.x);
    row[(((j0 + 1) ^ sw) << 2) + pos] = tf32r(v.y);
    row[(((j0 + 2) ^ sw) << 2) + pos] = tf32r(v.z);
    row[(((j0 + 3) ^ sw) << 2) + pos] = tf32r(v.w);
}
__device__ __forceinline__ void stp1(float* b0, float* b1, int e, int k, float v) {
    float* base = (e & 16) ? b1 : b0;
    int s = k >> 3;
    int j4 = ((e & 7) << 2) | (k & 3);
    int pos = ((e & 8) >> 3) | ((k & 4) >> 1);
    ((u32*)base)[s * 128 + (((j4 ^ (s & 7)) << 2) | pos)] = tf32r(v);
}

// ---------------- weight permute+tf32 prep ----------------
__global__ void prep_weights(const float* __restrict__ We2, const float* __restrict__ Wc2,
                             const float* __restrict__ Wlin, const float* __restrict__ Wa1,
                             const float* __restrict__ We1, const float* __restrict__ Wn1,
                             const float* __restrict__ Wn2, const float* __restrict__ Wc1) {
    int m = blockIdx.y;
    const float* src;
    switch (m) {
        case 0: src = We2; break;
        case 1: src = Wc2; break;
        case 2: src = Wlin; break;
        case 3: src = Wa1; break;
        case 4: src = Wa1 + 128 * 128; break;
        case 5: src = We1; break;
        case 6: src = Wn1; break;
        case 7: src = Wn2; break;
        case 8: src = Wc1; break;
        default: src = Wc1 + 128 * 128; break;
    }
    float* dst = g_Wp + m * WSZ;
    int idx = blockIdx.x * blockDim.x + threadIdx.x;
    if (idx >= 16 * 16 * 32) return;
    int l = idx & 31, nt = (idx >> 5) & 15, s = idx >> 9;
    int k0 = s * 8 + (l & 3);
    int cc = nt * 8 + (l >> 2);
    u32* d = (u32*)(dst + (s * 16 + nt) * 64 + l * 2);
    d[0] = tf32r(src[k0 * 128 + cc]);
    d[1] = tf32r(src[(k0 + 4) * 128 + cc]);
}

// ---------------- tf32 GEMM mainloop (evict_last weights) ----------------
__device__ __forceinline__ void gemm16(const float* sA0, const float* sA1,
                                       const float* __restrict__ gW,
                                       int lane, int w, float (*c)[4]) {
#pragma unroll 2
    for (int s = 0; s < 16; s++) {
        int li = lane ^ (s & 7);
        uint4 a0 = ((const uint4*)sA0)[s * 32 + li];
        uint4 a1 = ((const uint4*)sA1)[s * 32 + li];
        uint2 b[4];
#pragma unroll
        for (int j = 0; j < 4; j++)
            b[j] = ldg_w(gW + (s * 16 + w * 4 + j) * 64 + lane * 2);
#pragma unroll
        for (int j = 0; j < 4; j++) {
            mma8(c[j], a0, b[j]);
            mma8(c[4 + j], a1, b[j]);
        }
    }
}
__device__ __forceinline__ void init_bias(const float* __restrict__ bias,
                                          int lane, int w, float (*c)[4]) {
#pragma unroll
    for (int j = 0; j < 4; j++) {
        float2 bb = *(const float2*)(bias + w * 32 + j * 8 + (lane & 3) * 2);
        c[j][0] = bb.x; c[j][1] = bb.y; c[j][2] = bb.x; c[j][3] = bb.y;
        c[4 + j][0] = bb.x; c[4 + j][1] = bb.y; c[4 + j][2] = bb.x; c[4 + j][3] = bb.y;
    }
}
__device__ __forceinline__ void zero_c(float (*c)[4]) {
#pragma unroll
    for (int p = 0; p < 8; p++)
#pragma unroll
        for (int q = 0; q < 4; q++) c[p][q] = 0.f;
}
__device__ __forceinline__ void store_c_gmem(float (*c)[4], float* dst,
                                             int lane, int w) {
    int g = lane >> 2;
#pragma unroll
    for (int j = 0; j < 4; j++) {
        int n = w * 32 + j * 8 + (lane & 3) * 2;
#pragma unroll
        for (int m = 0; m < 2; m++) {
            int e = g + m * 16;
            *(float2*)(dst + e * D + n) = make_float2(c[m * 4 + j][0], c[m * 4 + j][1]);
            *(float2*)(dst + (e + 8) * D + n) = make_float2(c[m * 4 + j][2], c[m * 4 + j][3]);
        }
    }
}
__device__ __forceinline__ void frag_from_c(float (*c)[4], float* sF0, float* sF1,
                                            int lane, int w) {
    int g = lane >> 2;
#pragma unroll
    for (int j = 0; j < 4; j++) {
        int n = w * 32 + j * 8 + (lane & 3) * 2;
#pragma unroll
        for (int m = 0; m < 2; m++) {
            int e = g + m * 16;
            stp1(sF0, sF1, e, n, c[m * 4 + j][0]);
            stp1(sF0, sF1, e, n + 1, c[m * 4 + j][1]);
            stp1(sF0, sF1, e + 8, n, c[m * 4 + j][2]);
            stp1(sF0, sF1, e + 8, n + 1, c[m * 4 + j][3]);
        }
    }
}

// ---------------- node front: hh, P_r, P_c, Q projections; zero agg -------------
__global__ void __launch_bounds__(128)
node_front(const float* __restrict__ h, const float* __restrict__ blin) {
    __shared__ __align__(16) float sF[2 * FR16];
    float* sF0 = sF;
    float* sF1 = sF + FR16;
    int t = threadIdx.x, lane = t & 31, w = t >> 5;
    int r0 = blockIdx.x * TN;
    int c4 = lane << 2;

    // zero scatter targets for this block's rows (replaces zero_all kernel)
    float4 z4 = make_float4(0.f, 0.f, 0.f, 0.f);
#pragma unroll
    for (int i = 0; i < 8; i++) {
        int e = w * 8 + i;
        ((float4*)(g_agg + (r0 + e) * D))[lane] = z4;
    }
    if (t < TN) {
        g_as[r0 + t] = 0.f;
        g_aggx[(r0 + t) * 3 + 0] = 0.f;
        g_aggx[(r0 + t) * 3 + 1] = 0.f;
        g_aggx[(r0 + t) * 3 + 2] = 0.f;
    }

#pragma unroll
    for (int i = 0; i < 8; i++) {
        int e = w * 8 + i;
        float4 hv = ((const float4*)(h + (r0 + e) * D))[lane];
        stp4(sF0, sF1, e, c4, hv);
    }
    __syncthreads();

    float c[8][4];
    init_bias(blin, lane, w, c);
    gemm16(sF0, sF1, g_Wp + 2 * WSZ, lane, w, c);
    __syncthreads();

    store_c_gmem(c, g_hh + r0 * D, lane, w);
    frag_from_c(c, sF0, sF1, lane, w);
    __syncthreads();

    float cp[8][4];
    zero_c(cp);
    gemm16(sF0, sF1, g_Wp + 3 * WSZ, lane, w, cp);
    store_c_gmem(cp, g_Pr + r0 * D, lane, w);
    zero_c(cp);
    gemm16(sF0, sF1, g_Wp + 4 * WSZ, lane, w, cp);
    store_c_gmem(cp, g_Pc + r0 * D, lane, w);
    zero_c(cp);
    gemm16(sF0, sF1, g_Wp + 5 * WSZ, lane, w, cp);
    store_c_gmem(cp, g_Q + r0 * D, lane, w);
}

// ---------------- edge message + attention (no MMA; We2 hoisted) ----------------
__global__ void __launch_bounds__(128, 6)
edge_msg(const float* __restrict__ x, const int* __restrict__ ei,
         const float* __restrict__ edge_mask,
         const float* __restrict__ edge_attr,
         const float* __restrict__ Wa1, const float* __restrict__ ba1,
         const float* __restrict__ Wa2, const float* __restrict__ ba2,
         const float* __restrict__ We1, const float* __restrict__ be1) {
    __shared__ float s_d[32], s_ea[32], s_em[32];
    __shared__ int s_row[32], s_col[32];

    int t = threadIdx.x, lane = t & 31, w = t >> 5;
    int e0b = blockIdx.x * TE;

    if (t < TE) {
        int e = t;
        int r = ei[e0b + e];
        int c = ei[NE + e0b + e];
        s_row[e] = r;
        s_col[e] = c;
        s_em[e]  = edge_mask[e0b + e];
        float ea = edge_attr[e0b + e];
        s_ea[e]  = ea;
        float dx = x[r * 3 + 0] - x[c * 3 + 0];
        float dy = x[r * 3 + 1] - x[c * 3 + 1];
        float dz = x[r * 3 + 2] - x[c * 3 + 2];
        float dist = sqrtf(dx * dx + dy * dy + dz * dz + 1e-8f);
        s_d[e] = dist;
        g_e3[(e0b + e) * 3 + 0] = dist;
    }
    __syncthreads();

    {
        int c4 = lane << 2;
        float4 waD = *(const float4*)(Wa1 + 256 * 128 + c4);
        float4 waA = *(const float4*)(Wa1 + 257 * 128 + c4);
        float4 waG = *(const float4*)(Wa1 + 258 * 128 + c4);
        float4 bA  = *(const float4*)(ba1 + c4);
        float4 w2v = *(const float4*)(Wa2 + c4);
        float4 weD = *(const float4*)(We1 + 128 * 128 + c4);
        float4 weA = *(const float4*)(We1 + 129 * 128 + c4);
        float4 weG = *(const float4*)(We1 + 130 * 128 + c4);
        float4 bM  = *(const float4*)(be1 + c4);
        float b2 = ba2[0];
#pragma unroll
        for (int i = 0; i < 8; i++) {
            int e = w * 8 + i;
            int r = s_row[e], c = s_col[e];
            float4 hr = ldg_s(g_hh + r * D + c4);
            float4 hc = ldg_s(g_hh + c * D + c4);
            float vx = hc.x - hr.x, vy = hc.y - hr.y;
            float vz = hc.z - hr.z, vw = hc.w - hr.w;
            float q = vx * vx + vy * vy + vz * vz + vw * vw;
#pragma unroll
            for (int o = 16; o > 0; o >>= 1) q += __shfl_xor_sync(0xffffffffu, q, o);
            float gg = sqrtf(q + 1e-8f);
            float dd = s_d[e], ea = s_ea[e];
            float4 pr = ldg_s(g_Pr + r * D + c4);
            float4 pc = ldg_s(g_Pc + c * D + c4);
            float4 qr = ldg_s(g_Q + r * D + c4);
            float4 qc = ldg_s(g_Q + c * D + c4);
            float a0 = pr.x + pc.x + dd * waD.x + ea * waA.x + gg * waG.x + bA.x;
            float a1 = pr.y + pc.y + dd * waD.y + ea * waA.y + gg * waG.y + bA.y;
            float a2 = pr.z + pc.z + dd * waD.z + ea * waA.z + gg * waG.z + bA.z;
            float a3 = pr.w + pc.w + dd * waD.w + ea * waA.w + gg * waG.w + bA.w;
            float p = siluf(a0) * w2v.x + siluf(a1) * w2v.y +
                      siluf(a2) * w2v.z + siluf(a3) * w2v.w;
#pragma unroll
            for (int o = 16; o > 0; o >>= 1) p += __shfl_xor_sync(0xffffffffu, p, o);
            float att = __fdividef(s_em[e], 1.f + __expf(-(p + b2)));
            float m0 = siluf(qc.x - qr.x + dd * weD.x + ea * weA.x + gg * weG.x + bM.x) * att;
            float m1 = siluf(qc.y - qr.y + dd * weD.y + ea * weA.y + gg * weG.y + bM.y) * att;
            float m2 = siluf(qc.z - qr.z + dd * weD.z + ea * weA.z + gg * weG.z + bM.z) * att;
            float m3 = siluf(qc.w - qr.w + dd * weD.w + ea * weA.w + gg * weG.w + bM.w) * att;
            red4(&g_agg[r * D + c4], m0, m1, m2, m3);
            if (lane == 0) {
                atomicAdd(&g_as[r], att);
                g_e3[(e0b + e) * 3 + 2] = gg;
            }
        }
    }
}

// ---------------- node MLP: We2 stage + residual + LN + silu ; R projections ----
__global__ void __launch_bounds__(128)
node_mlp(const float* __restrict__ be2,
         const float* __restrict__ bn1, const float* __restrict__ bn2,
         const float* __restrict__ ln_g, const float* __restrict__ ln_b,
         float* __restrict__ out_h) {
    __shared__ __align__(16) float sF[2 * FR16];
    __shared__ float s_ps[TN * 4], s_pq[TN * 4], s_mu[TN], s_rs[TN], s_as[TN];
    float* sF0 = sF;
    float* sF1 = sF + FR16;
    int t = threadIdx.x, lane = t & 31, w = t >> 5;
    int g = lane >> 2;
    int r0 = blockIdx.x * TN;
    int c4 = lane << 2;

    if (t < TN) s_as[t] = g_as[r0 + t];
#pragma unroll
    for (int i = 0; i < 8; i++) {
        int e = w * 8 + i;
        float4 zv = ((const float4*)(g_agg + (r0 + e) * D))[lane];
        stp4(sF0, sF1, e, c4, zv);
    }
    __syncthreads();

    // agg = z @ We2 + be2 * sum_att
    float c0[8][4];
    zero_c(c0);
    gemm16(sF0, sF1, g_Wp + 0 * WSZ, lane, w, c0);
    __syncthreads();
#pragma unroll
    for (int j = 0; j < 4; j++) {
        int n = w * 32 + j * 8 + (lane & 3) * 2;
        float2 bv = *(const float2*)(be2 + n);
#pragma unroll
        for (int m = 0; m < 2; m++) {
            int e = g + m * 16;
            float aL = s_as[e], aH = s_as[e + 8];
            c0[m * 4 + j][0] += bv.x * aL;
            c0[m * 4 + j][1] += bv.y * aL;
            c0[m * 4 + j][2] += bv.x * aH;
            c0[m * 4 + j][3] += bv.y * aH;
        }
    }
    frag_from_c(c0, sF0, sF1, lane, w);
    __syncthreads();

    float c1[8][4];
    init_bias(bn1, lane, w, c1);
    gemm16(sF0, sF1, g_Wp + 6 * WSZ, lane, w, c1);
    __syncthreads();

#pragma unroll
    for (int p = 0; p < 8; p++)
#pragma unroll
        for (int q = 0; q < 4; q++) c1[p][q] = siluf(c1[p][q]);
    frag_from_c(c1, sF0, sF1, lane, w);
    __syncthreads();

    float c2[8][4];
    init_bias(bn2, lane, w, c2);
    gemm16(sF0, sF1, g_Wp + 7 * WSZ, lane, w, c2);

#pragma unroll
    for (int j = 0; j < 4; j++) {
        int n = w * 32 + j * 8 + (lane & 3) * 2;
#pragma unroll
        for (int m = 0; m < 2; m++) {
            int e = g + m * 16;
            float2 h0 = *(const float2*)(g_hh + (r0 + e) * D + n);
            float2 h1 = *(const float2*)(g_hh + (r0 + e + 8) * D + n);
            c2[m * 4 + j][0] += h0.x;
            c2[m * 4 + j][1] += h0.y;
            c2[m * 4 + j][2] += h1.x;
            c2[m * 4 + j][3] += h1.y;
        }
    }

    {
        float su[4] = {0.f, 0.f, 0.f, 0.f};
        float sq[4] = {0.f, 0.f, 0.f, 0.f};
#pragma unroll
        for (int j = 0; j < 4; j++) {
#pragma unroll
            for (int m = 0; m < 2; m++) {
                float v0 = c2[m * 4 + j][0], v1 = c2[m * 4 + j][1];
                float v2 = c2[m * 4 + j][2], v3 = c2[m * 4 + j][3];
                su[m * 2 + 0] += v0 + v1;
                sq[m * 2 + 0] += v0 * v0 + v1 * v1;
                su[m * 2 + 1] += v2 + v3;
                sq[m * 2 + 1] += v2 * v2 + v3 * v3;
            }
        }
#pragma unroll
        for (int i = 0; i < 4; i++) {
            su[i] += __shfl_down_sync(0xffffffffu, su[i], 2, 4);
            su[i] += __shfl_down_sync(0xffffffffu, su[i], 1, 4);
            sq[i] += __shfl_down_sync(0xffffffffu, sq[i], 2, 4);
            sq[i] += __shfl_down_sync(0xffffffffu, sq[i], 1, 4);
        }
        if ((lane & 3) == 0) {
            s_ps[(g) * 4 + w]      = su[0];
            s_pq[(g) * 4 + w]      = sq[0];
            s_ps[(g + 8) * 4 + w]  = su[1];
            s_pq[(g + 8) * 4 + w]  = sq[1];
            s_ps[(g + 16) * 4 + w] = su[2];
            s_pq[(g + 16) * 4 + w] = sq[2];
            s_ps[(g + 24) * 4 + w] = su[3];
            s_pq[(g + 24) * 4 + w] = sq[3];
        }
    }
    __syncthreads();
    if (t < TN) {
        float s = s_ps[t * 4] + s_ps[t * 4 + 1] + s_ps[t * 4 + 2] + s_ps[t * 4 + 3];
        float q = s_pq[t * 4] + s_pq[t * 4 + 1] + s_pq[t * 4 + 2] + s_pq[t * 4 + 3];
        float mu = s * (1.f / 128.f);
        float var = q * (1.f / 128.f) - mu * mu;
        s_mu[t] = mu;
        s_rs[t] = rsqrtf(var + 1e-5f);
    }
    __syncthreads();

#pragma unroll
    for (int j = 0; j < 4; j++) {
        int n = w * 32 + j * 8 + (lane & 3) * 2;
        float2 gv = *(const float2*)(ln_g + n);
        float2 bv = *(const float2*)(ln_b + n);
#pragma unroll
        for (int m = 0; m < 2; m++) {
            int e = g + m * 16;
            float muL = s_mu[e], rsL = s_rs[e];
            float muH = s_mu[e + 8], rsH = s_rs[e + 8];
            float v0 = siluf((c2[m * 4 + j][0] - muL) * rsL * gv.x + bv.x);
            float v1 = siluf((c2[m * 4 + j][1] - muL) * rsL * gv.y + bv.y);
            float v2 = siluf((c2[m * 4 + j][2] - muH) * rsH * gv.x + bv.x);
            float v3 = siluf((c2[m * 4 + j][3] - muH) * rsH * gv.y + bv.y);
            *(float2*)(out_h + (r0 + e) * D + n) = make_float2(v0, v1);
            *(float2*)(out_h + (r0 + e + 8) * D + n) = make_float2(v2, v3);
            c2[m * 4 + j][0] = v0;
            c2[m * 4 + j][1] = v1;
            c2[m * 4 + j][2] = v2;
            c2[m * 4 + j][3] = v3;
        }
    }
    frag_from_c(c2, sF0, sF1, lane, w);
    __syncthreads();

    float cr[8][4];
    zero_c(cr);
    gemm16(sF0, sF1, g_Wp + 8 * WSZ, lane, w, cr);
    store_c_gmem(cr, g_Rr + r0 * D, lane, w);
    zero_c(cr);
    gemm16(sF0, sF1, g_Wp + 9 * WSZ, lane, w, cr);
    store_c_gmem(cr, g_Rc + r0 * D, lane, w);
}

// ---------------- coord MLP + scatter ----------------
__global__ void __launch_bounds__(128, 6)
edge_coord(const float* __restrict__ x, const int* __restrict__ ei,
           const float* __restrict__ edge_mask,
           const float* __restrict__ edge_attr,
           const float* __restrict__ Wc1, const float* __restrict__ bc1,
           const float* __restrict__ bc2, const float* __restrict__ Wc3) {
    extern __shared__ float sm[];
    float* sA0   = sm;
    float* sA1   = sA0 + FR16;
    float* s_gp  = sA1 + FR16;
    float* s_d   = s_gp + 128;
    float* s_ea  = s_d + 32;
    float* s_geo = s_ea + 32;
    float* s_em  = s_geo + 32;
    int*   s_row = (int*)(s_em + 32);
    int*   s_col = s_row + 32;

    int t = threadIdx.x, lane = t & 31, w = t >> 5;
    int e0b = blockIdx.x * TE;

    if (t < TE) {
        s_row[t] = ei[e0b + t];
        s_col[t] = ei[NE + e0b + t];
        s_em[t]  = edge_mask[e0b + t];
        s_ea[t]  = edge_attr[e0b + t];
        s_d[t]   = g_e3[(e0b + t) * 3 + 0];
        s_geo[t] = g_e3[(e0b + t) * 3 + 2];
    }
    __syncthreads();

    {
        int c4 = lane << 2;
        float4 wcD = *(const float4*)(Wc1 + 256 * 128 + c4);
        float4 wcA = *(const float4*)(Wc1 + 257 * 128 + c4);
        float4 wcG = *(const float4*)(Wc1 + 258 * 128 + c4);
        float4 bC  = *(const float4*)(bc1 + c4);
#pragma unroll
        for (int i = 0; i < 8; i++) {
            int e = w * 8 + i;
            int r = s_row[e], c = s_col[e];
            float4 rr = ldg_s(g_Rr + r * D + c4);
            float4 rc = ldg_s(g_Rc + c * D + c4);
            float dd = s_d[e], ea = s_ea[e], gg = s_geo[e];
            float4 cv;
            cv.x = siluf(rr.x + rc.x + dd * wcD.x + ea * wcA.x + gg * wcG.x + bC.x);
            cv.y = siluf(rr.y + rc.y + dd * wcD.y + ea * wcA.y + gg * wcG.y + bC.y);
            cv.z = siluf(rr.z + rc.z + dd * wcD.z + ea * wcA.z + gg * wcG.z + bC.z);
            cv.w = siluf(rr.w + rc.w + dd * wcD.w + ea * wcA.w + gg * wcG.w + bC.w);
            stp4(sA0, sA1, e, c4, cv);
        }
    }
    __syncthreads();

    float c2[8][4];
    init_bias(bc2, lane, w, c2);
    gemm16(sA0, sA1, g_Wp + 1 * WSZ, lane, w, c2);

    {
        float p0 = 0.f, p1 = 0.f, p2 = 0.f, p3 = 0.f;
#pragma unroll
        for (int j = 0; j < 4; j++) {
            float2 w3 = *(const float2*)(Wc3 + w * 32 + j * 8 + (lane & 3) * 2);
            p0 += siluf(c2[j][0]) * w3.x + siluf(c2[j][1]) * w3.y;
            p1 += siluf(c2[j][2]) * w3.x + siluf(c2[j][3]) * w3.y;
            p2 += siluf(c2[4 + j][0]) * w3.x + siluf(c2[4 + j][1]) * w3.y;
            p3 += siluf(c2[4 + j][2]) * w3.x + siluf(c2[4 + j][3]) * w3.y;
        }
        p0 += __shfl_down_sync(0xffffffffu, p0, 2, 4); p0 += __shfl_down_sync(0xffffffffu, p0, 1, 4);
        p1 += __shfl_down_sync(0xffffffffu, p1, 2, 4); p1 += __shfl_down_sync(0xffffffffu, p1, 1, 4);
        p2 += __shfl_down_sync(0xffffffffu, p2, 2, 4); p2 += __shfl_down_sync(0xffffffffu, p2, 1, 4);
        p3 += __shfl_down_sync(0xffffffffu, p3, 2, 4); p3 += __shfl_down_sync(0xffffffffu, p3, 1, 4);
        if ((lane & 3) == 0) {
            int g = lane >> 2;
            s_gp[g * 4 + w]        = p0;
            s_gp[(g + 8) * 4 + w]  = p1;
            s_gp[(g + 16) * 4 + w] = p2;
            s_gp[(g + 24) * 4 + w] = p3;
        }
    }
    __syncthreads();

    if (t < TE) {
        int e = t;
        float mval = (s_gp[e * 4] + s_gp[e * 4 + 1] + s_gp[e * 4 + 2] + s_gp[e * 4 + 3])
                     * s_em[e];
        int r = s_row[e], c = s_col[e];
        float dx = x[r * 3 + 0] - x[c * 3 + 0];
        float dy = x[r * 3 + 1] - x[c * 3 + 1];
        float dz = x[r * 3 + 2] - x[c * 3 + 2];
        float inv = 1.f / (s_d[e] + 1.f);
        atomicAdd(&g_aggx[r * 3 + 0], dx * inv * mval);
        atomicAdd(&g_aggx[r * 3 + 1], dy * inv * mval);
        atomicAdd(&g_aggx[r * 3 + 2], dz * inv * mval);
    }
}

__global__ void finalize_x(const float* __restrict__ x,
                           const float* __restrict__ node_mask,
                           float* __restrict__ out) {
    int i = blockIdx.x * blockDim.x + threadIdx.x;
    if (i < NN * 3) {
        out[i] = (x[i] + g_aggx[i] * (1.f / 100.f)) * node_mask[i / 3];
    }
}

// ---------------- launcher ----------------
extern "C" void kernel_launch(void* const* d_in, const int* in_sizes, int n_in,
                              void* d_out, int out_size) {
    const float* h         = (const float*)d_in[0];
    const float* x         = (const float*)d_in[1];
    const int*   ei        = (const int*)d_in[2];
    const float* node_mask = (const float*)d_in[3];
    const float* edge_mask = (const float*)d_in[4];
    const float* edge_attr = (const float*)d_in[5];
    const float* Wlin = (const float*)d_in[6];
    const float* blin = (const float*)d_in[7];
    const float* We1  = (const float*)d_in[8];
    const float* be1  = (const float*)d_in[9];
    const float* We2  = (const float*)d_in[10];
    const float* be2  = (const float*)d_in[11];
    const float* Wn1  = (const float*)d_in[12];
    const float* bn1  = (const float*)d_in[13];
    const float* Wn2  = (const float*)d_in[14];
    const float* bn2  = (const float*)d_in[15];
    const float* Wa1  = (const float*)d_in[16];
    const float* ba1  = (const float*)d_in[17];
    const float* Wa2  = (const float*)d_in[18];
    const float* ba2  = (const float*)d_in[19];
    const float* ln_g = (const float*)d_in[20];
    const float* ln_b = (const float*)d_in[21];
    const float* Wc1  = (const float*)d_in[22];
    const float* bc1  = (const float*)d_in[23];
    const float* Wc2  = (const float*)d_in[24];
    const float* bc2  = (const float*)d_in[25];
    const float* Wc3  = (const float*)d_in[26];
    float* out = (float*)d_out;

    const int SMEM_CRD = (2 * FR16 + 128 + 4 * 32) * 4 + 2 * 32 * 4;
    cudaFuncSetAttribute(edge_coord, cudaFuncAttributeMaxDynamicSharedMemorySize, SMEM_CRD);

    prep_weights<<<dim3(32, 10), 256>>>(We2, Wc2, Wlin, Wa1, We1, Wn1, Wn2, Wc1);
    node_front<<<NN / TN, 128>>>(h, blin);
    edge_msg<<<NE / TE, 128>>>(x, ei, edge_mask, edge_attr,
                               Wa1, ba1, Wa2, ba2, We1, be1);
    node_mlp<<<NN / TN, 128>>>(be2, bn1, bn2, ln_g, ln_b, out);
    edge_coord<<<NE / TE, 128, SMEM_CRD>>>(x, ei, edge_mask, edge_attr,
                                           Wc1, bc1, bc2, Wc3);
    finalize_x<<<(NN * 3 + 255) / 256, 256>>>(x, node_mask, out + NN * D);
}